// round 15
// baseline (speedup 1.0000x reference)
#include <cuda_runtime.h>
#include <cuda_bf16.h>
#include <cstdint>

// ---------------------------------------------------------------------------
// GIN encoder: 3 x (GINConv(sum-agg) -> MLP(64,relu,64) -> relu -> BN) -> add-pool
// Round 15 = round-14 base (260us best) + paired-fragment smem layout:
//   * k_mlp was L1-bound (54%) on 96 LDS.64/thread/tile. Permute the k-word
//     order everywhere: perm(w) = (w&~7) | ((w&3)<<1) | ((w&4)>>2) so each
//     MMA fragment pair (kt*8+tig, kt*8+tig+4) is ADJACENT -> one LDS.128.
//     48 loads instead of 96. Permutation applied at write time (k_agg
//     output, W staging, h epilogue); cp.async copies verbatim.
//   * pitch KP2 36 -> 40: all LDS.128 phases conflict-free.
//   * __launch_bounds__(256,3): pin regs under the 3-blocks/SM cliff (R13).
// Kept: persistent 444-block k_mlp, inline BN coefs (no k_bnfin), fp32
// float2 ELL gather, bf16x3 m16n8k16, sorted-batch pool. Fusion banned.
// ---------------------------------------------------------------------------

#define MAXN 131072
#define ELLW 64
#define KP2  40                 // smem pitch in uint2 words

__device__ int   g_cursor[MAXN];
__device__ int   g_ell[(size_t)MAXN * ELLW];
__device__ float g_rA[(size_t)MAXN * 64];
__device__ float g_rB[(size_t)MAXN * 64];
__device__ uint2 g_aggP[(size_t)MAXN * 32];   // packed bf16 (hi,lo), PERMUTED cols
__device__ float g_stats[3 * 128];   // per layer: [0:64) sum, [64:128) sumsq

// k-word permutation: fragment pair (kt*8+tig, kt*8+tig+4) -> adjacent slots
__device__ __forceinline__ int permw(int w) {
    return (w & ~7) | ((w & 3) << 1) | ((w & 4) >> 2);
}

// split (ev,od) floats into packed-bf16 hi word (ev low half) + lo word
__device__ __forceinline__ void bf16split2(float ev, float od,
                                           uint32_t& hi, uint32_t& lo) {
    __nv_bfloat16 he = __float2bfloat16_rn(ev);
    __nv_bfloat16 ho = __float2bfloat16_rn(od);
    float le = ev - __bfloat162float(he);
    float lo_f = od - __bfloat162float(ho);
    __nv_bfloat162 ph, pl;
    ph.x = he; ph.y = ho;
    pl.x = __float2bfloat16_rn(le); pl.y = __float2bfloat16_rn(lo_f);
    hi = *(uint32_t*)&ph;
    lo = *(uint32_t*)&pl;
}

__device__ __forceinline__ void mma_bf16(float c[4],
    uint32_t a0, uint32_t a1, uint32_t a2, uint32_t a3,
    uint32_t b0, uint32_t b1)
{
    asm volatile(
        "mma.sync.aligned.m16n8k16.row.col.f32.bf16.bf16.f32 "
        "{%0,%1,%2,%3}, {%4,%5,%6,%7}, {%8,%9}, {%0,%1,%2,%3};"
        : "+f"(c[0]), "+f"(c[1]), "+f"(c[2]), "+f"(c[3])
        : "r"(a0), "r"(a1), "r"(a2), "r"(a3), "r"(b0), "r"(b1));
}

__device__ __forceinline__ void cp_async16(void* sdst, const void* gsrc) {
    uint32_t s = (uint32_t)__cvta_generic_to_shared(sdst);
    asm volatile("cp.async.cg.shared.global [%0], [%1], 16;" :: "r"(s), "l"(gsrc));
}

// BN affine for feature f of layer l: out = a*h + b
__device__ __forceinline__ void bn_coef(const float* __restrict__ gamma,
                                        const float* __restrict__ beta,
                                        int layer, int f, float invN,
                                        float& a, float& b) {
    const float* st = &g_stats[layer * 128];
    float mean = st[f] * invN;
    float var  = fmaxf(st[64 + f] * invN - mean * mean, 0.f);
    a = gamma[f] * rsqrtf(var + 1e-5f);
    b = beta[f] - mean * a;
}

// ---------------------------- build ----------------------------------------

__global__ void k_zero(int N) {
    int i = blockIdx.x * blockDim.x + threadIdx.x;
    if (i < N)   g_cursor[i] = 0;
    if (i < 384) g_stats[i]  = 0.f;
}

__global__ void k_fill(const int* __restrict__ src, const int* __restrict__ dst, int E) {
    int e = blockIdx.x * blockDim.x + threadIdx.x;
    if (e < E) {
        int d = dst[e];
        int p = atomicAdd(&g_cursor[d], 1);
        if (p < ELLW) g_ell[(size_t)d * ELLW + p] = src[e];
    }
}

// ---------------------------- aggregation -----------------------------------
// 1 warp/node, float2/lane, ELL indices via coalesced load + shfl.
// Output stored at PERMUTED column permw(lane) (bijection, still coalesced).
__global__ __launch_bounds__(256) void k_agg(
    const float* __restrict__ x, int insel /*0=x,1=rA,2=rB*/, int layer,
    const float* __restrict__ gamma, const float* __restrict__ beta, int N)
{
    int gt   = blockIdx.x * blockDim.x + threadIdx.x;
    int node = gt >> 5;
    int lane = gt & 31;
    if (node >= N) return;

    const float2* __restrict__ inp =
        (insel == 0) ? (const float2*)x :
        (insel == 1) ? (const float2*)g_rA : (const float2*)g_rB;

    float a0c = 1.f, a1c = 1.f, b0c = 0.f, b1c = 0.f;
    if (layer > 0) {
        float invN = 1.f / (float)N;
        bn_coef(gamma, beta, layer - 1, 2 * lane,     invN, a0c, b0c);
        bn_coef(gamma, beta, layer - 1, 2 * lane + 1, invN, a1c, b1c);
    }

    float2 acc = inp[(size_t)node * 32 + lane];   // self term
    int deg = min(g_cursor[node], ELLW);
    const int* cols = g_ell + (size_t)node * ELLW;
    int c0 = cols[lane];
    int c1 = cols[lane + 32];

    int d0 = min(deg, 32);
    int e = 0;
    for (; e + 3 < d0; e += 4) {
        int s0 = __shfl_sync(0xffffffffu, c0, e);
        int s1 = __shfl_sync(0xffffffffu, c0, e + 1);
        int s2 = __shfl_sync(0xffffffffu, c0, e + 2);
        int s3 = __shfl_sync(0xffffffffu, c0, e + 3);
        float2 v0 = inp[(size_t)s0 * 32 + lane];
        float2 v1 = inp[(size_t)s1 * 32 + lane];
        float2 v2 = inp[(size_t)s2 * 32 + lane];
        float2 v3 = inp[(size_t)s3 * 32 + lane];
        acc.x += (v0.x + v1.x) + (v2.x + v3.x);
        acc.y += (v0.y + v1.y) + (v2.y + v3.y);
    }
    for (; e < d0; e++) {
        int s = __shfl_sync(0xffffffffu, c0, e);
        float2 v = inp[(size_t)s * 32 + lane];
        acc.x += v.x;
        acc.y += v.y;
    }
    int d1 = deg - 32;
    for (int e2 = 0; e2 < d1; e2++) {
        int s = __shfl_sync(0xffffffffu, c1, e2);
        float2 v = inp[(size_t)s * 32 + lane];
        acc.x += v.x;
        acc.y += v.y;
    }

    if (layer > 0) {
        float cnt = (float)(deg + 1);
        acc.x = a0c * acc.x + cnt * b0c;
        acc.y = a1c * acc.y + cnt * b1c;
    }
    uint32_t hi, lo;
    bf16split2(acc.x, acc.y, hi, lo);
    g_aggP[(size_t)node * 32 + permw(lane)] = make_uint2(hi, lo);
}

// ---------------- bf16x3 tensor-core MLP, paired-fragment LDS.128 -----------
// 256 threads (8 warps), persistent grid-stride (444 blocks = 3/SM exactly).
// Warp tile m16 x n32. dyn smem: Q1 (W1), Q2 (W2), P (A / h), all permuted.
__global__ __launch_bounds__(256, 3) void k_mlp(
    const float* __restrict__ wa, const float* __restrict__ ba,
    const float* __restrict__ wb, const float* __restrict__ bb,
    int outsel /*1=rA,2=rB*/, int layer, int N)
{
    extern __shared__ uint2 dyn[];
    uint2* Q1 = dyn;
    uint2* Q2 = dyn + 64 * KP2;
    uint2* P  = dyn + 2 * 64 * KP2;
    __shared__ float B1s[64], B2s[64];
    __shared__ float ssum[64], ssq[64];

    float* rout = (outsel == 1) ? g_rA : g_rB;
    int t    = threadIdx.x;
    int lane = t & 31, warp = t >> 5;
    int gid  = lane >> 2, tig = lane & 3;
    int mi   = warp & 3,  ni  = warp >> 2;

    // stage W1 + W2 once per block (permuted columns)
#pragma unroll
    for (int i = 0; i < 8; i++) {
        int idx = t + 256 * i;        // 0..2047
        int n = idx & 63, kp = idx >> 6;
        int pc = permw(kp);
        uint32_t hi, lo;
        bf16split2(wa[(2 * kp) * 64 + n], wa[(2 * kp + 1) * 64 + n], hi, lo);
        Q1[n * KP2 + pc] = make_uint2(hi, lo);
        bf16split2(wb[(2 * kp) * 64 + n], wb[(2 * kp + 1) * 64 + n], hi, lo);
        Q2[n * KP2 + pc] = make_uint2(hi, lo);
    }
    if (t < 64) { B1s[t] = ba[t]; B2s[t] = bb[t]; ssum[t] = 0.f; ssq[t] = 0.f; }
    __syncthreads();

    // fragment base offsets (uint2 units); uint4 loads read pairs
    int arow0 = (mi * 16 + gid) * KP2 + 2 * tig;
    int brow0 = (ni * 32 + gid) * KP2 + 2 * tig;

    // per-thread BN-stat accumulators across tiles
    float ts[8], tq[8];
#pragma unroll
    for (int i = 0; i < 8; i++) { ts[i] = 0.f; tq[i] = 0.f; }

    int ntile = (N + 63) >> 6;
#pragma unroll 1
    for (int tile = blockIdx.x; tile < ntile; tile += gridDim.x) {
        int m0 = tile * 64;

        // stage A tile via cp.async (layout already permuted in global)
#pragma unroll
        for (int j = 0; j < 4; j++) {
            int idx = t + 256 * j;         // 0..1023
            int row = idx >> 4;
            int cp  = (idx & 15) * 2;      // uint2 pair index
            cp_async16(&P[row * KP2 + cp], &g_aggP[(size_t)(m0 + row) * 32 + cp]);
        }
        asm volatile("cp.async.commit_group;");
        asm volatile("cp.async.wait_group 0;" ::: "memory");
        __syncthreads();

        float c[4][4];
#pragma unroll
        for (int nt = 0; nt < 4; nt++)
#pragma unroll
            for (int i = 0; i < 4; i++) c[nt][i] = 0.f;

        // GEMM1: all fragment loads are LDS.128 {w0.hi, w0.lo, w1.hi, w1.lo}
#pragma unroll
        for (int kt = 0; kt < 4; kt++) {
            uint4 q0 = *(const uint4*)&P[arow0 + kt * 8];            // a0, a2
            uint4 q1 = *(const uint4*)&P[arow0 + 8 * KP2 + kt * 8];  // a1, a3
#pragma unroll
            for (int nt = 0; nt < 4; nt++) {
                uint4 r = *(const uint4*)&Q1[brow0 + nt * 8 * KP2 + kt * 8];
                mma_bf16(c[nt], q0.x, q1.x, q0.z, q1.z, r.x, r.z);  // hi*hi
                mma_bf16(c[nt], q0.x, q1.x, q0.z, q1.z, r.y, r.w);  // hi*lo
                mma_bf16(c[nt], q0.y, q1.y, q0.w, q1.w, r.x, r.z);  // lo*hi
            }
        }
        __syncthreads();   // all P reads (A) done

        // h = relu(c + b1) -> P at permuted columns
#pragma unroll
        for (int nt = 0; nt < 4; nt++) {
            int n0 = ni * 32 + nt * 8 + 2 * tig;
            float bb0 = B1s[n0], bb1 = B1s[n0 + 1];
            int r0 = mi * 16 + gid;
            int pc = permw(n0 >> 1);
            uint32_t hi, lo;
            bf16split2(fmaxf(c[nt][0] + bb0, 0.f), fmaxf(c[nt][1] + bb1, 0.f), hi, lo);
            P[r0 * KP2 + pc] = make_uint2(hi, lo);
            bf16split2(fmaxf(c[nt][2] + bb0, 0.f), fmaxf(c[nt][3] + bb1, 0.f), hi, lo);
            P[(r0 + 8) * KP2 + pc] = make_uint2(hi, lo);
#pragma unroll
            for (int i = 0; i < 4; i++) c[nt][i] = 0.f;
        }
        __syncthreads();

        // GEMM2
#pragma unroll
        for (int kt = 0; kt < 4; kt++) {
            uint4 q0 = *(const uint4*)&P[arow0 + kt * 8];
            uint4 q1 = *(const uint4*)&P[arow0 + 8 * KP2 + kt * 8];
#pragma unroll
            for (int nt = 0; nt < 4; nt++) {
                uint4 r = *(const uint4*)&Q2[brow0 + nt * 8 * KP2 + kt * 8];
                mma_bf16(c[nt], q0.x, q1.x, q0.z, q1.z, r.x, r.z);
                mma_bf16(c[nt], q0.x, q1.x, q0.z, q1.z, r.y, r.w);
                mma_bf16(c[nt], q0.y, q1.y, q0.w, q1.w, r.x, r.z);
            }
        }

        // epilogue: relu + bias2, store fp32, accumulate BN stats in registers
        int gr0 = m0 + mi * 16 + gid, gr1 = gr0 + 8;
        bool ok0 = gr0 < N, ok1 = gr1 < N;
#pragma unroll
        for (int nt = 0; nt < 4; nt++) {
            int n0 = ni * 32 + nt * 8 + 2 * tig;
            float bb0 = B2s[n0], bb1 = B2s[n0 + 1];
            float v00 = fmaxf(c[nt][0] + bb0, 0.f);
            float v01 = fmaxf(c[nt][1] + bb1, 0.f);
            float v10 = fmaxf(c[nt][2] + bb0, 0.f);
            float v11 = fmaxf(c[nt][3] + bb1, 0.f);
            if (ok0) {
                *(float2*)&rout[(size_t)gr0 * 64 + n0] = make_float2(v00, v01);
                ts[2 * nt]     += v00; tq[2 * nt]     += v00 * v00;
                ts[2 * nt + 1] += v01; tq[2 * nt + 1] += v01 * v01;
            }
            if (ok1) {
                *(float2*)&rout[(size_t)gr1 * 64 + n0] = make_float2(v10, v11);
                ts[2 * nt]     += v10; tq[2 * nt]     += v10 * v10;
                ts[2 * nt + 1] += v11; tq[2 * nt + 1] += v11 * v11;
            }
        }
        __syncthreads();   // P reads done before next tile restages
    }

    // one smem-atomic stats pass per block, then global flush
#pragma unroll
    for (int nt = 0; nt < 4; nt++) {
        int n0 = ni * 32 + nt * 8 + 2 * tig;
        atomicAdd(&ssum[n0],     ts[2 * nt]);
        atomicAdd(&ssq[n0],      tq[2 * nt]);
        atomicAdd(&ssum[n0 + 1], ts[2 * nt + 1]);
        atomicAdd(&ssq[n0 + 1],  tq[2 * nt + 1]);
    }
    __syncthreads();
    if (t < 64) {
        atomicAdd(&g_stats[layer * 128 + t],      ssum[t]);
        atomicAdd(&g_stats[layer * 128 + 64 + t], ssq[t]);
    }
}

// ---------------------------- pool ------------------------------------------
// batch sorted: run-length accumulate, atomics only at graph boundaries.
// Layer-3 BN affine computed inline from g_stats.
__global__ void k_pool(int insel /*1=rA,2=rB*/, const int* __restrict__ batch,
                       const float* __restrict__ gamma, const float* __restrict__ beta,
                       float* __restrict__ out, int N) {
    const float2* r = (insel == 1) ? (const float2*)g_rA : (const float2*)g_rB;
    int t   = threadIdx.x;  // 256
    int w   = t & 31;
    int sub = t >> 5;       // 0..7
    float invN = 1.f / (float)N;
    float a0, b0, a1, b1;
    bn_coef(gamma, beta, 2, 2 * w,     invN, a0, b0);
    bn_coef(gamma, beta, 2, 2 * w + 1, invN, a1, b1);
    int n0  = blockIdx.x * 256;
    int nend = min(n0 + 256, N);
    float2 acc = make_float2(0.f, 0.f);
    int curg = -1;
    for (int n = n0 + sub; n < nend; n += 8) {
        int g = batch[n];
        if (g != curg) {
            if (curg >= 0) {
                atomicAdd(&out[curg * 64 + 2 * w],     acc.x);
                atomicAdd(&out[curg * 64 + 2 * w + 1], acc.y);
            }
            curg = g;
            acc = make_float2(0.f, 0.f);
        }
        float2 v = r[(size_t)n * 32 + w];
        acc.x += fmaf(a0, v.x, b0);
        acc.y += fmaf(a1, v.y, b1);
    }
    if (curg >= 0) {
        atomicAdd(&out[curg * 64 + 2 * w],     acc.x);
        atomicAdd(&out[curg * 64 + 2 * w + 1], acc.y);
    }
}

// ---------------------------- launch ----------------------------------------
extern "C" void kernel_launch(void* const* d_in, const int* in_sizes, int n_in,
                              void* d_out, int out_size) {
    const float* x     = (const float*)d_in[0];
    const int*   ei    = (const int*)d_in[1];
    const int*   batch = (const int*)d_in[2];

    const float* WA[3] = {(const float*)d_in[3],  (const float*)d_in[9],  (const float*)d_in[15]};
    const float* BA[3] = {(const float*)d_in[4],  (const float*)d_in[10], (const float*)d_in[16]};
    const float* WB[3] = {(const float*)d_in[5],  (const float*)d_in[11], (const float*)d_in[17]};
    const float* BB[3] = {(const float*)d_in[6],  (const float*)d_in[12], (const float*)d_in[18]};
    const float* GM[3] = {(const float*)d_in[7],  (const float*)d_in[13], (const float*)d_in[19]};
    const float* BE[3] = {(const float*)d_in[8],  (const float*)d_in[14], (const float*)d_in[20]};

    int N = in_sizes[0] / 64;
    int E = in_sizes[1] / 2;
    const int* src = ei;
    const int* dst = ei + E;

    const int DYN = 3 * 64 * KP2 * (int)sizeof(uint2);   // 61440 B
    cudaFuncSetAttribute(k_mlp, cudaFuncAttributeMaxDynamicSharedMemorySize, DYN);
    cudaFuncSetAttribute(k_mlp, cudaFuncAttributePreferredSharedMemoryCarveout, 100);

    // build: zero cursor/stats, ELL adjacency
    k_zero<<<(N + 255) / 256, 256>>>(N);
    k_fill<<<(E + 255) / 256, 256>>>(src, dst, E);

    // 3 GIN layers (no k_bnfin; BN coefs inline in consumers)
    int ntile = (N + 63) / 64;
    int mgrid = 444 < ntile ? 444 : ntile;   // 148 SMs x 3 blocks
    int insel = 0;  // x
    for (int L = 0; L < 3; L++) {
        int outsel = (L & 1) ? 2 : 1;  // L0->rA, L1->rB, L2->rA
        const float* pg = (L > 0) ? GM[L - 1] : GM[0];
        const float* pb = (L > 0) ? BE[L - 1] : BE[0];
        k_agg<<<((size_t)N * 32 + 255) / 256, 256>>>(x, insel, L, pg, pb, N);
        k_mlp<<<mgrid, 256, DYN>>>(WA[L], BA[L], WB[L], BB[L], outsel, L, N);
        insel = outsel;
    }

    cudaMemsetAsync(d_out, 0, (size_t)out_size * sizeof(float));
    k_pool<<<(N + 255) / 256, 256>>>(insel, batch, GM[2], BE[2], (float*)d_out, N);
}